// round 2
// baseline (speedup 1.0000x reference)
#include <cuda_runtime.h>
#include <cuda_bf16.h>
#include <math.h>

// ---------------- problem constants ----------------
#define BB   16384
#define TT   4
#define FF   7
#define EE   64
#define HH   128
#define G4   512        // 4*H
#define NNB  32         // neighbors
#define NH   4
#define HD   32
#define KK   3

// output layout: traj (B*36), probs (B*3), attn_weights (B*32)
#define TRAJ_OFF 0
#define PROB_OFF (BB * 36)
#define AW_OFF   (BB * 36 + BB * 3)

// padded shared strides (even => 8B-aligned float pairs)
#define SWS 514         // 512-col weight tile stride
#define SWA 258         // 256-col weight tile stride (attn)
#define SKV 130         // k/v tile stride

// ---------------- scratch (__device__ globals; no cudaMalloc allowed) ----------------
static __device__ float g_preact_x[BB * TT * G4];   // 134 MB
static __device__ float g_h[BB * HH];
static __device__ float g_c[BB * HH];
static __device__ float g_hn[BB * NNB * HH];        // 268 MB

__device__ __forceinline__ float sigf(float x) {
    return 1.0f / (1.0f + __expf(-x));
}

// ---- packed f32x2 helpers ----
__device__ __forceinline__ void ffma2(unsigned long long& d,
                                      unsigned long long a,
                                      unsigned long long b) {
    asm("fma.rn.f32x2 %0, %1, %2, %0;" : "+l"(d) : "l"(a), "l"(b));
}
__device__ __forceinline__ unsigned long long dup2(float x) {
    unsigned long long r;
    unsigned u = __float_as_uint(x);
    asm("mov.b64 %0, {%1, %1};" : "=l"(r) : "r"(u));
    return r;
}
__device__ __forceinline__ float2 unpk(unsigned long long v) {
    unsigned lo, hi;
    asm("mov.b64 {%0, %1}, %2;" : "=r"(lo), "=r"(hi) : "l"(v));
    return make_float2(__uint_as_float(lo), __uint_as_float(hi));
}

// =====================================================================
// Kernel 1: target embed + input GEMM (rows = B*T, 32 rows x 512 cols, K=64)
//   preact_x[row, col] = relu(x_row @ embed_W^T + embed_b) @ W_ih^T
//   thread (c, tr): columns are pairs at 2c + 64m, m = 0..7
// =====================================================================
__global__ void k_target_in(const float* __restrict__ x,
                            const float* __restrict__ embW,
                            const float* __restrict__ embB,
                            const float* __restrict__ W_ih) {
    extern __shared__ float sm[];
    float* sW = sm;                      // 64*SWS
    float* sE = sm + 64 * SWS;           // 32*64
    float* sX = sE + 32 * 64;            // 32*8
    const int tid  = threadIdx.x;
    const int row0 = blockIdx.x * 32;

    for (int i = tid; i < G4 * EE; i += 256) {
        int g = i >> 6, e = i & 63;
        sW[e * SWS + g] = W_ih[i];
    }
    for (int i = tid; i < 32 * FF; i += 256) {
        int r = i / FF, f = i % FF;
        sX[r * 8 + f] = x[(row0 + r) * FF + f];
    }
    __syncthreads();
    for (int i = tid; i < 32 * EE; i += 256) {
        int r = i >> 6, e = i & 63;
        float a = embB[e];
        #pragma unroll
        for (int f = 0; f < FF; f++) a += sX[r * 8 + f] * embW[e * FF + f];
        sE[i] = fmaxf(a, 0.0f);
    }
    __syncthreads();

    const int c  = tid & 31;
    const int tr = tid >> 5;
    unsigned long long acc2[4][8];
    #pragma unroll
    for (int i = 0; i < 4; i++)
        #pragma unroll
        for (int m = 0; m < 8; m++) acc2[i][m] = 0ull;

    for (int e = 0; e < EE; e++) {
        unsigned long long em2[4];
        #pragma unroll
        for (int i = 0; i < 4; i++) em2[i] = dup2(sE[(tr + 8 * i) * 64 + e]);
        const float* wr = &sW[e * SWS + 2 * c];
        #pragma unroll
        for (int m = 0; m < 8; m++) {
            unsigned long long wp = *(const unsigned long long*)(wr + 64 * m);
            #pragma unroll
            for (int i = 0; i < 4; i++) ffma2(acc2[i][m], em2[i], wp);
        }
    }
    #pragma unroll
    for (int i = 0; i < 4; i++) {
        int row = row0 + tr + 8 * i;
        #pragma unroll
        for (int m = 0; m < 8; m++) {
            float2 v = unpk(acc2[i][m]);
            *(float2*)&g_preact_x[row * G4 + 2 * c + 64 * m] = v;
        }
    }
}

// =====================================================================
// Kernel 2: LSTM step 0 (h=c=0): gates from preact_x[:,0,:] + bias only
// =====================================================================
__global__ void k_lstm0(const float* __restrict__ b_ih,
                        const float* __restrict__ b_hh) {
    int idx = blockIdx.x * blockDim.x + threadIdx.x;
    if (idx >= BB * HH) return;
    int b = idx >> 7, u = idx & 127;
    const float* px = &g_preact_x[(b * TT) * G4];
    float iv = sigf(px[u] + b_ih[u] + b_hh[u]);
    float gv = tanhf(px[256 + u] + b_ih[256 + u] + b_hh[256 + u]);
    float ov = sigf(px[384 + u] + b_ih[384 + u] + b_hh[384 + u]);
    float cn = iv * gv;
    g_c[idx] = cn;
    g_h[idx] = ov * tanhf(cn);
}

// =====================================================================
// Kernel 3: LSTM step t (t=1..3): preact_h = h @ W_hh^T fused with gates.
//   32 batch rows x 512 cols, K=128 in two 64-wide smem stages.
//   Unit pair u = 64j + 2c{,+1}: gates at m = j, j+2, j+4, j+6 (register-local).
// =====================================================================
__global__ void k_lstm_step(const float* __restrict__ W_hh,
                            const float* __restrict__ b_ih,
                            const float* __restrict__ b_hh,
                            int t) {
    extern __shared__ float sm[];
    float* sW = sm;                 // 64*SWS
    float* sH = sm + 64 * SWS;      // 32*128
    const int tid = threadIdx.x;
    const int b0  = blockIdx.x * 32;

    for (int i = tid; i < 32 * HH; i += 256) sH[i] = g_h[b0 * HH + i];

    const int c  = tid & 31;
    const int tr = tid >> 5;
    unsigned long long acc2[4][8];
    #pragma unroll
    for (int i = 0; i < 4; i++)
        #pragma unroll
        for (int m = 0; m < 8; m++) acc2[i][m] = 0ull;

    for (int half = 0; half < 2; half++) {
        __syncthreads();   // sH visible (half 0) / sW reads done (half 1)
        for (int i = tid; i < G4 * 64; i += 256) {
            int g = i >> 6, e = i & 63;
            sW[e * SWS + g] = W_hh[g * HH + half * 64 + e];
        }
        __syncthreads();
        for (int e = 0; e < 64; e++) {
            unsigned long long em2[4];
            #pragma unroll
            for (int i = 0; i < 4; i++)
                em2[i] = dup2(sH[(tr + 8 * i) * HH + half * 64 + e]);
            const float* wr = &sW[e * SWS + 2 * c];
            #pragma unroll
            for (int m = 0; m < 8; m++) {
                unsigned long long wp = *(const unsigned long long*)(wr + 64 * m);
                #pragma unroll
                for (int i = 0; i < 4; i++) ffma2(acc2[i][m], em2[i], wp);
            }
        }
    }

    #pragma unroll
    for (int i = 0; i < 4; i++) {
        int b = b0 + tr + 8 * i;
        const float* px = &g_preact_x[(b * TT + t) * G4];
        #pragma unroll
        for (int j = 0; j < 2; j++) {
            int u = 64 * j + 2 * c;
            float2 ai = unpk(acc2[i][j]);
            float2 af = unpk(acc2[i][j + 2]);
            float2 ag = unpk(acc2[i][j + 4]);
            float2 ao = unpk(acc2[i][j + 6]);
            float2 pxi = *(const float2*)&px[u];
            float2 pxf = *(const float2*)&px[128 + u];
            float2 pxg = *(const float2*)&px[256 + u];
            float2 pxo = *(const float2*)&px[384 + u];
            float2 b1i = *(const float2*)&b_ih[u],       b2i = *(const float2*)&b_hh[u];
            float2 b1f = *(const float2*)&b_ih[128 + u], b2f = *(const float2*)&b_hh[128 + u];
            float2 b1g = *(const float2*)&b_ih[256 + u], b2g = *(const float2*)&b_hh[256 + u];
            float2 b1o = *(const float2*)&b_ih[384 + u], b2o = *(const float2*)&b_hh[384 + u];
            float2 cp = *(const float2*)&g_c[b * HH + u];
            float2 cn, hn;
            {
                float iv = sigf(ai.x + pxi.x + b1i.x + b2i.x);
                float fv = sigf(af.x + pxf.x + b1f.x + b2f.x);
                float gv = tanhf(ag.x + pxg.x + b1g.x + b2g.x);
                float ov = sigf(ao.x + pxo.x + b1o.x + b2o.x);
                cn.x = fv * cp.x + iv * gv;
                hn.x = ov * tanhf(cn.x);
            }
            {
                float iv = sigf(ai.y + pxi.y + b1i.y + b2i.y);
                float fv = sigf(af.y + pxf.y + b1f.y + b2f.y);
                float gv = tanhf(ag.y + pxg.y + b1g.y + b2g.y);
                float ov = sigf(ao.y + pxo.y + b1o.y + b2o.y);
                cn.y = fv * cp.y + iv * gv;
                hn.y = ov * tanhf(cn.y);
            }
            *(float2*)&g_c[b * HH + u] = cn;
            *(float2*)&g_h[b * HH + u] = hn;
        }
    }
}

// =====================================================================
// Kernel 4: neighbor encoder. Block = one batch b (32 neighbor rows x 512 cols),
//   fused embed + W_ih GEMM + zero-state LSTM gates -> g_hn (B*N, 128).
// =====================================================================
__global__ void k_neighbor(const float* __restrict__ nb,
                           const float* __restrict__ embW,
                           const float* __restrict__ embB,
                           const float* __restrict__ W_ih,
                           const float* __restrict__ b_ih,
                           const float* __restrict__ b_hh) {
    extern __shared__ float sm[];
    float* sW = sm;                      // 64*SWS
    float* sE = sm + 64 * SWS;           // 32*64
    float* sX = sE + 32 * 64;            // 32*8
    const int tid  = threadIdx.x;
    const int b    = blockIdx.x;
    const int row0 = b * NNB;

    for (int i = tid; i < G4 * EE; i += 256) {
        int g = i >> 6, e = i & 63;
        sW[e * SWS + g] = W_ih[i];
    }
    for (int i = tid; i < 32 * FF; i += 256) {
        int r = i / FF, f = i % FF;
        sX[r * 8 + f] = nb[(row0 + r) * FF + f];
    }
    __syncthreads();
    for (int i = tid; i < 32 * EE; i += 256) {
        int r = i >> 6, e = i & 63;
        float a = embB[e];
        #pragma unroll
        for (int f = 0; f < FF; f++) a += sX[r * 8 + f] * embW[e * FF + f];
        sE[i] = fmaxf(a, 0.0f);
    }
    __syncthreads();

    const int c  = tid & 31;
    const int tr = tid >> 5;
    unsigned long long acc2[4][8];
    #pragma unroll
    for (int i = 0; i < 4; i++)
        #pragma unroll
        for (int m = 0; m < 8; m++) acc2[i][m] = 0ull;

    for (int e = 0; e < EE; e++) {
        unsigned long long em2[4];
        #pragma unroll
        for (int i = 0; i < 4; i++) em2[i] = dup2(sE[(tr + 8 * i) * 64 + e]);
        const float* wr = &sW[e * SWS + 2 * c];
        #pragma unroll
        for (int m = 0; m < 8; m++) {
            unsigned long long wp = *(const unsigned long long*)(wr + 64 * m);
            #pragma unroll
            for (int i = 0; i < 4; i++) ffma2(acc2[i][m], em2[i], wp);
        }
    }
    #pragma unroll
    for (int i = 0; i < 4; i++) {
        int gr = row0 + tr + 8 * i;   // global neighbor row
        #pragma unroll
        for (int j = 0; j < 2; j++) {
            int u = 64 * j + 2 * c;
            float2 ai = unpk(acc2[i][j]);
            float2 ag = unpk(acc2[i][j + 4]);
            float2 ao = unpk(acc2[i][j + 6]);
            float2 b1i = *(const float2*)&b_ih[u],       b2i = *(const float2*)&b_hh[u];
            float2 b1g = *(const float2*)&b_ih[256 + u], b2g = *(const float2*)&b_hh[256 + u];
            float2 b1o = *(const float2*)&b_ih[384 + u], b2o = *(const float2*)&b_hh[384 + u];
            float2 hn;
            {
                float iv = sigf(ai.x + b1i.x + b2i.x);
                float gv = tanhf(ag.x + b1g.x + b2g.x);
                float ov = sigf(ao.x + b1o.x + b2o.x);
                float cn = iv * gv;
                hn.x = ov * tanhf(cn);
            }
            {
                float iv = sigf(ai.y + b1i.y + b2i.y);
                float gv = tanhf(ag.y + b1g.y + b2g.y);
                float ov = sigf(ao.y + b1o.y + b2o.y);
                float cn = iv * gv;
                hn.y = ov * tanhf(cn);
            }
            *(float2*)&g_hn[gr * HH + u] = hn;
        }
    }
}

// =====================================================================
// Kernel 5: per-batch fused attention + heads. Block = one b, 256 threads.
// =====================================================================
__global__ void k_attn(const float* __restrict__ ipw,
                       const float* __restrict__ ipb,
                       const float* __restrict__ opw,
                       const float* __restrict__ opb,
                       const int*   __restrict__ cnts,
                       const float* __restrict__ tW1,
                       const float* __restrict__ tb1,
                       const float* __restrict__ tW2,
                       const float* __restrict__ tb2,
                       const float* __restrict__ pW,
                       const float* __restrict__ pb,
                       float* __restrict__ out) {
    extern __shared__ float sm[];
    float* sW   = sm;                     // 128*SWA  (Wk|Wv transposed)
    float* sHn  = sW  + 128 * SWA;        // 32*129
    float* sK   = sHn + 32 * 129;         // 32*SKV
    float* sV   = sK  + 32 * SKV;         // 32*SKV
    float* sHt  = sV  + 32 * SKV;         // 128
    float* sQ   = sHt + 128;              // 128
    float* sWg  = sQ  + 128;              // 128  [head*32+n]
    float* sAt  = sWg + 128;              // 128
    float* sHc  = sAt + 128;              // 256
    float* sHid = sHc + 256;              // 128
    float* sLg  = sHid + 128;             // 4

    const int tid = threadIdx.x;
    const int b   = blockIdx.x;

    // stage Wk,Wv (in_proj rows 128..383) transposed: sW[e*SWA + j]
    for (int i = tid; i < 256 * HH; i += 256) {
        int j = i >> 7, e = i & 127;
        sW[e * SWA + j] = ipw[HH * HH + i];   // ipw[(128+j)*128 + e]
    }
    for (int i = tid; i < NNB * HH; i += 256) {
        int n = i >> 7, col = i & 127;
        sHn[n * 129 + col] = g_hn[(b * NNB + n) * HH + col];
    }
    if (tid < HH) sHt[tid] = g_h[b * HH + tid];
    __syncthreads();

    // ---- k/v GEMM: 32 rows x 256 cols, K=128, f32x2 pairs at 2c + 64m ----
    const int c  = tid & 31;
    const int tr = tid >> 5;
    unsigned long long acc2[4][4];
    #pragma unroll
    for (int i = 0; i < 4; i++)
        #pragma unroll
        for (int m = 0; m < 4; m++) acc2[i][m] = 0ull;

    for (int e = 0; e < HH; e++) {
        unsigned long long em2[4];
        #pragma unroll
        for (int i = 0; i < 4; i++) em2[i] = dup2(sHn[(tr + 8 * i) * 129 + e]);
        const float* wr = &sW[e * SWA + 2 * c];
        #pragma unroll
        for (int m = 0; m < 4; m++) {
            unsigned long long wp = *(const unsigned long long*)(wr + 64 * m);
            #pragma unroll
            for (int i = 0; i < 4; i++) ffma2(acc2[i][m], em2[i], wp);
        }
    }
    #pragma unroll
    for (int i = 0; i < 4; i++) {
        int r = tr + 8 * i;
        #pragma unroll
        for (int j = 0; j < 2; j++) {
            int u = 2 * c + 64 * j;
            float2 vk = unpk(acc2[i][j]);
            float2 bk = *(const float2*)&ipb[128 + u];
            sK[r * SKV + u]     = vk.x + bk.x;
            sK[r * SKV + u + 1] = vk.y + bk.y;
            float2 vv = unpk(acc2[i][j + 2]);
            float2 bv = *(const float2*)&ipb[256 + u];
            sV[r * SKV + u]     = vv.x + bv.x;
            sV[r * SKV + u + 1] = vv.y + bv.y;
        }
    }
    __syncthreads();

    // ---- q = h_t @ Wq^T + bq ----
    if (tid < HH) {
        float a = ipb[tid];
        const float* w = &ipw[tid * HH];
        #pragma unroll 8
        for (int h = 0; h < HH; h++) a = fmaf(sHt[h], w[h], a);
        sQ[tid] = a;
    }
    __syncthreads();

    const int cnt = cnts[b];

    // ---- scores + masked softmax (warp per head) ----
    if (tid < 128) {
        int n = tid & 31, hd = tid >> 5;
        float s = 0.0f;
        #pragma unroll
        for (int d = 0; d < HD; d++)
            s = fmaf(sQ[hd * 32 + d], sK[n * SKV + hd * 32 + d], s);
        s *= 0.17677669529663689f;       // 1/sqrt(32)
        s = (n < cnt) ? s : -1e9f;
        float mx = s;
        #pragma unroll
        for (int o = 16; o > 0; o >>= 1)
            mx = fmaxf(mx, __shfl_xor_sync(0xffffffffu, mx, o));
        float ev = __expf(s - mx);
        float sum = ev;
        #pragma unroll
        for (int o = 16; o > 0; o >>= 1)
            sum += __shfl_xor_sync(0xffffffffu, sum, o);
        sWg[tid] = ev / sum;
    }
    __syncthreads();

    // ---- attn = sum_n w[head,n] * v[n, :] ----
    if (tid < 128) {
        int hd = tid >> 5;
        float a = 0.0f;
        #pragma unroll
        for (int n = 0; n < NNB; n++)
            a = fmaf(sWg[hd * 32 + n], sV[n * SKV + tid], a);
        sAt[tid] = a;
    }
    __syncthreads();

    // ---- out_proj + h_comb; attn_weights ----
    if (tid < 128) {
        float a = opb[tid];
        const float* w = &opw[tid * HH];
        #pragma unroll 8
        for (int h = 0; h < HH; h++) a = fmaf(sAt[h], w[h], a);
        sHc[tid]       = sHt[tid];
        sHc[128 + tid] = (cnt > 0) ? a : 0.0f;
    }
    if (tid < 32) {
        float aw = 0.25f * (sWg[tid] + sWg[32 + tid] + sWg[64 + tid] + sWg[96 + tid]);
        out[AW_OFF + b * NNB + tid] = (tid < cnt) ? aw : 0.0f;
    }
    __syncthreads();

    // ---- traj hidden ----
    if (tid < 128) {
        float a = tb1[tid];
        const float* w = &tW1[tid * 256];
        #pragma unroll 8
        for (int h = 0; h < 256; h++) a = fmaf(sHc[h], w[h], a);
        sHid[tid] = fmaxf(a, 0.0f);
    }
    __syncthreads();

    // ---- traj output + prob logits (disjoint thread ranges) ----
    if (tid < 36) {
        float a = tb2[tid];
        const float* w = &tW2[tid * HH];
        #pragma unroll 8
        for (int j = 0; j < HH; j++) a = fmaf(sHid[j], w[j], a);
        out[TRAJ_OFF + b * 36 + tid] = a;
    }
    if (tid >= 64 && tid < 64 + KK) {
        int k = tid - 64;
        float a = pb[k];
        const float* w = &pW[k * 256];
        #pragma unroll 8
        for (int h = 0; h < 256; h++) a = fmaf(sHc[h], w[h], a);
        sLg[k] = a;
    }
    __syncthreads();
    if (tid < KK) {
        float m = fmaxf(sLg[0], fmaxf(sLg[1], sLg[2]));
        float e0 = __expf(sLg[0] - m);
        float e1 = __expf(sLg[1] - m);
        float e2 = __expf(sLg[2] - m);
        out[PROB_OFF + b * KK + tid] = __expf(sLg[tid] - m) / (e0 + e1 + e2);
    }
}

// =====================================================================
// Launch
// =====================================================================
extern "C" void kernel_launch(void* const* d_in, const int* in_sizes, int n_in,
                              void* d_out, int out_size) {
    (void)in_sizes; (void)n_in; (void)out_size;
    const float* x    = (const float*)d_in[0];
    const float* nb   = (const float*)d_in[1];
    const int*   cnts = (const int*)  d_in[2];
    const float* embW = (const float*)d_in[3];
    const float* embB = (const float*)d_in[4];
    const float* W_ih = (const float*)d_in[5];
    const float* W_hh = (const float*)d_in[6];
    const float* b_ih = (const float*)d_in[7];
    const float* b_hh = (const float*)d_in[8];
    const float* ipw  = (const float*)d_in[9];
    const float* ipb  = (const float*)d_in[10];
    const float* opw  = (const float*)d_in[11];
    const float* opb  = (const float*)d_in[12];
    const float* tW1  = (const float*)d_in[13];
    const float* tb1  = (const float*)d_in[14];
    const float* tW2  = (const float*)d_in[15];
    const float* tb2  = (const float*)d_in[16];
    const float* pW   = (const float*)d_in[17];
    const float* pb   = (const float*)d_in[18];
    float* out = (float*)d_out;

    const int SM_T = (64 * SWS + 32 * 64 + 32 * 8) * 4;
    const int SM_L = (64 * SWS + 32 * 128) * 4;
    const int SM_A = (128 * SWA + 32 * 129 + 2 * 32 * SKV + 5 * 128 + 256 + 4) * 4;

    cudaFuncSetAttribute(k_target_in, cudaFuncAttributeMaxDynamicSharedMemorySize, SM_T);
    cudaFuncSetAttribute(k_lstm_step, cudaFuncAttributeMaxDynamicSharedMemorySize, SM_L);
    cudaFuncSetAttribute(k_neighbor,  cudaFuncAttributeMaxDynamicSharedMemorySize, SM_T);
    cudaFuncSetAttribute(k_attn,      cudaFuncAttributeMaxDynamicSharedMemorySize, SM_A);

    // target chain
    k_target_in<<<(BB * TT) / 32, 256, SM_T>>>(x, embW, embB, W_ih);
    k_lstm0<<<(BB * HH + 255) / 256, 256>>>(b_ih, b_hh);
    for (int t = 1; t < TT; t++)
        k_lstm_step<<<BB / 32, 256, SM_L>>>(W_hh, b_ih, b_hh, t);

    // neighbor chain
    k_neighbor<<<BB, 256, SM_T>>>(nb, embW, embB, W_ih, b_ih, b_hh);

    // fused attention + heads
    k_attn<<<BB, 256, SM_A>>>(ipw, ipb, opw, opb, cnts,
                              tW1, tb1, tW2, tb2, pW, pb, out);
}

// round 6
// speedup vs baseline: 1.4247x; 1.4247x over previous
#include <cuda_runtime.h>
#include <cuda_bf16.h>
#include <math.h>

// ---------------- problem constants ----------------
#define BB   16384
#define TT   4
#define FF   7
#define EE   64
#define HH   128
#define G4   512        // 4*H
#define NNB  32         // neighbors
#define NH   4
#define HD   32
#define KK   3

// output layout: traj (B*36), probs (B*3), attn_weights (B*32)
#define TRAJ_OFF 0
#define PROB_OFF (BB * 36)
#define AW_OFF   (BB * 36 + BB * 3)

#define SWT 258         // 256-col weight tile stride (even -> aligned pairs)
#define SWK 130         // 128-col weight tile stride (kv kernel)

// ---------------- scratch (__device__ globals) ----------------
static __device__ float g_preact_x[BB * TT * G4];       // 134 MB
static __device__ float g_h[BB * HH];
static __device__ float g_c[BB * HH];
static __device__ float g_hn[BB * NNB * HH];            // 268 MB
static __device__ float g_kv[BB * NNB * 2 * HH];        // 536 MB (K | V per row)

__device__ __forceinline__ float sigf(float x) {
    return 1.0f / (1.0f + __expf(-x));
}

// ---- packed f32x2 helpers ----
__device__ __forceinline__ void ffma2(unsigned long long& d,
                                      unsigned long long a,
                                      unsigned long long b) {
    asm("fma.rn.f32x2 %0, %1, %2, %0;" : "+l"(d) : "l"(a), "l"(b));
}
__device__ __forceinline__ unsigned long long dup2(float x) {
    unsigned long long r;
    unsigned u = __float_as_uint(x);
    asm("mov.b64 %0, {%1, %1};" : "=l"(r) : "r"(u));
    return r;
}
__device__ __forceinline__ float2 unpk(unsigned long long v) {
    unsigned lo, hi;
    asm("mov.b64 {%0, %1}, %2;" : "=r"(lo), "=r"(hi) : "l"(v));
    return make_float2(__uint_as_float(lo), __uint_as_float(hi));
}

// =====================================================================
// Kernel 1: target embed + input GEMM, unit-split.
//   grid = (BT/64) * 2.  block: 512 thr, 64 rows x 256 cols, K=64.
//   CTA col-half ch covers units u0=ch*64..+63 for ALL 4 gates:
//   local col = gt*64 + j  <->  global col = 128*gt + u0 + j
// =====================================================================
__global__ __launch_bounds__(512, 2)
void k_target_in(const float* __restrict__ x,
                 const float* __restrict__ embW,
                 const float* __restrict__ embB,
                 const float* __restrict__ W_ih) {
    extern __shared__ float sm[];
    float* sW = sm;                      // 64*SWT
    float* sE = sm + 64 * SWT;           // 64*64
    float* sX = sE + 64 * 64;            // 64*8
    const int tid  = threadIdx.x;
    const int ch   = blockIdx.x & 1;
    const int row0 = (blockIdx.x >> 1) * 64;
    const int u0   = ch * 64;

    for (int i = tid; i < 256 * 64; i += 512) {
        int e = i & 63, col = i >> 6;
        int gt = col >> 6, j = col & 63;
        sW[e * SWT + col] = W_ih[(128 * gt + u0 + j) * EE + e];
    }
    for (int i = tid; i < 64 * FF; i += 512) {
        int r = i / FF, f = i % FF;
        sX[r * 8 + f] = x[(row0 + r) * FF + f];
    }
    __syncthreads();
    for (int i = tid; i < 64 * EE; i += 512) {
        int r = i >> 6, e = i & 63;
        float a = embB[e];
        #pragma unroll
        for (int f = 0; f < FF; f++) a += sX[r * 8 + f] * embW[e * FF + f];
        sE[i] = fmaxf(a, 0.0f);
    }
    __syncthreads();

    const int c  = tid & 31;
    const int tr = tid >> 5;             // 0..15
    unsigned long long acc2[4][4];
    #pragma unroll
    for (int i = 0; i < 4; i++)
        #pragma unroll
        for (int m = 0; m < 4; m++) acc2[i][m] = 0ull;

    #pragma unroll 4
    for (int e = 0; e < EE; e++) {
        unsigned long long em2[4];
        #pragma unroll
        for (int i = 0; i < 4; i++) em2[i] = dup2(sE[(tr + 16 * i) * 64 + e]);
        const float* wr = &sW[e * SWT + 2 * c];
        #pragma unroll
        for (int m = 0; m < 4; m++) {
            unsigned long long wp = *(const unsigned long long*)(wr + 64 * m);
            #pragma unroll
            for (int i = 0; i < 4; i++) ffma2(acc2[i][m], em2[i], wp);
        }
    }
    #pragma unroll
    for (int i = 0; i < 4; i++) {
        int row = row0 + tr + 16 * i;
        #pragma unroll
        for (int gt = 0; gt < 4; gt++) {
            float2 v = unpk(acc2[i][gt]);
            *(float2*)&g_preact_x[row * G4 + 128 * gt + u0 + 2 * c] = v;
        }
    }
}

// =====================================================================
// Kernel 2: LSTM step 0 (h=c=0)
// =====================================================================
__global__ void k_lstm0(const float* __restrict__ b_ih,
                        const float* __restrict__ b_hh) {
    int idx = blockIdx.x * blockDim.x + threadIdx.x;
    if (idx >= BB * HH) return;
    int b = idx >> 7, u = idx & 127;
    const float* px = &g_preact_x[(b * TT) * G4];
    float iv = sigf(px[u] + b_ih[u] + b_hh[u]);
    float gv = tanhf(px[256 + u] + b_ih[256 + u] + b_hh[256 + u]);
    float ov = sigf(px[384 + u] + b_ih[384 + u] + b_hh[384 + u]);
    float cn = iv * gv;
    g_c[idx] = cn;
    g_h[idx] = ov * tanhf(cn);
}

// =====================================================================
// Kernel 3: LSTM step t: h @ W_hh^T fused with gates, unit-split.
//   grid = (B/64)*2.  64 rows x 256 cols, K=128 in two 64-wide stages.
// =====================================================================
__global__ __launch_bounds__(512, 2)
void k_lstm_step(const float* __restrict__ W_hh,
                 const float* __restrict__ b_ih,
                 const float* __restrict__ b_hh,
                 int t) {
    extern __shared__ float sm[];
    float* sW = sm;                 // 64*SWT
    float* sH = sm + 64 * SWT;      // 64*128
    const int tid = threadIdx.x;
    const int ch  = blockIdx.x & 1;
    const int b0  = (blockIdx.x >> 1) * 64;
    const int u0  = ch * 64;

    for (int i = tid; i < 64 * HH; i += 512) sH[i] = g_h[b0 * HH + i];

    const int c  = tid & 31;
    const int tr = tid >> 5;
    unsigned long long acc2[4][4];
    #pragma unroll
    for (int i = 0; i < 4; i++)
        #pragma unroll
        for (int m = 0; m < 4; m++) acc2[i][m] = 0ull;

    for (int half = 0; half < 2; half++) {
        __syncthreads();
        for (int i = tid; i < 256 * 64; i += 512) {
            int e = i & 63, col = i >> 6;
            int gt = col >> 6, j = col & 63;
            sW[e * SWT + col] = W_hh[(128 * gt + u0 + j) * HH + half * 64 + e];
        }
        __syncthreads();
        #pragma unroll 4
        for (int e = 0; e < 64; e++) {
            unsigned long long em2[4];
            #pragma unroll
            for (int i = 0; i < 4; i++)
                em2[i] = dup2(sH[(tr + 16 * i) * HH + half * 64 + e]);
            const float* wr = &sW[e * SWT + 2 * c];
            #pragma unroll
            for (int m = 0; m < 4; m++) {
                unsigned long long wp = *(const unsigned long long*)(wr + 64 * m);
                #pragma unroll
                for (int i = 0; i < 4; i++) ffma2(acc2[i][m], em2[i], wp);
            }
        }
    }

    #pragma unroll
    for (int i = 0; i < 4; i++) {
        int b = b0 + tr + 16 * i;
        const float* px = &g_preact_x[(b * TT + t) * G4];
        int u = u0 + 2 * c;
        float2 ai = unpk(acc2[i][0]);
        float2 af = unpk(acc2[i][1]);
        float2 ag = unpk(acc2[i][2]);
        float2 ao = unpk(acc2[i][3]);
        float2 pxi = *(const float2*)&px[u];
        float2 pxf = *(const float2*)&px[128 + u];
        float2 pxg = *(const float2*)&px[256 + u];
        float2 pxo = *(const float2*)&px[384 + u];
        float2 b1i = *(const float2*)&b_ih[u],       b2i = *(const float2*)&b_hh[u];
        float2 b1f = *(const float2*)&b_ih[128 + u], b2f = *(const float2*)&b_hh[128 + u];
        float2 b1g = *(const float2*)&b_ih[256 + u], b2g = *(const float2*)&b_hh[256 + u];
        float2 b1o = *(const float2*)&b_ih[384 + u], b2o = *(const float2*)&b_hh[384 + u];
        float2 cp = *(const float2*)&g_c[b * HH + u];
        float2 cn, hn;
        {
            float iv = sigf(ai.x + pxi.x + b1i.x + b2i.x);
            float fv = sigf(af.x + pxf.x + b1f.x + b2f.x);
            float gv = tanhf(ag.x + pxg.x + b1g.x + b2g.x);
            float ov = sigf(ao.x + pxo.x + b1o.x + b2o.x);
            cn.x = fv * cp.x + iv * gv;
            hn.x = ov * tanhf(cn.x);
        }
        {
            float iv = sigf(ai.y + pxi.y + b1i.y + b2i.y);
            float fv = sigf(af.y + pxf.y + b1f.y + b2f.y);
            float gv = tanhf(ag.y + pxg.y + b1g.y + b2g.y);
            float ov = sigf(ao.y + pxo.y + b1o.y + b2o.y);
            cn.y = fv * cp.y + iv * gv;
            hn.y = ov * tanhf(cn.y);
        }
        *(float2*)&g_c[b * HH + u] = cn;
        *(float2*)&g_h[b * HH + u] = hn;
    }
}

// =====================================================================
// Kernel 4: neighbor encoder, unit-split. 64 rows/block over B*N rows.
//   grid = (B*N/64)*2.  fused embed + W_ih GEMM + zero-state gates -> g_hn.
// =====================================================================
__global__ __launch_bounds__(512, 2)
void k_neighbor(const float* __restrict__ nb,
                const float* __restrict__ embW,
                const float* __restrict__ embB,
                const float* __restrict__ W_ih,
                const float* __restrict__ b_ih,
                const float* __restrict__ b_hh) {
    extern __shared__ float sm[];
    float* sW = sm;                      // 64*SWT
    float* sE = sm + 64 * SWT;           // 64*64
    float* sX = sE + 64 * 64;            // 64*8
    const int tid  = threadIdx.x;
    const int ch   = blockIdx.x & 1;
    const int row0 = (blockIdx.x >> 1) * 64;
    const int u0   = ch * 64;

    for (int i = tid; i < 256 * 64; i += 512) {
        int e = i & 63, col = i >> 6;
        int gt = col >> 6, j = col & 63;
        sW[e * SWT + col] = W_ih[(128 * gt + u0 + j) * EE + e];
    }
    for (int i = tid; i < 64 * FF; i += 512) {
        int r = i / FF, f = i % FF;
        sX[r * 8 + f] = nb[(row0 + r) * FF + f];
    }
    __syncthreads();
    for (int i = tid; i < 64 * EE; i += 512) {
        int r = i >> 6, e = i & 63;
        float a = embB[e];
        #pragma unroll
        for (int f = 0; f < FF; f++) a += sX[r * 8 + f] * embW[e * FF + f];
        sE[i] = fmaxf(a, 0.0f);
    }
    __syncthreads();

    const int c  = tid & 31;
    const int tr = tid >> 5;
    unsigned long long acc2[4][4];
    #pragma unroll
    for (int i = 0; i < 4; i++)
        #pragma unroll
        for (int m = 0; m < 4; m++) acc2[i][m] = 0ull;

    #pragma unroll 4
    for (int e = 0; e < EE; e++) {
        unsigned long long em2[4];
        #pragma unroll
        for (int i = 0; i < 4; i++) em2[i] = dup2(sE[(tr + 16 * i) * 64 + e]);
        const float* wr = &sW[e * SWT + 2 * c];
        #pragma unroll
        for (int m = 0; m < 4; m++) {
            unsigned long long wp = *(const unsigned long long*)(wr + 64 * m);
            #pragma unroll
            for (int i = 0; i < 4; i++) ffma2(acc2[i][m], em2[i], wp);
        }
    }
    #pragma unroll
    for (int i = 0; i < 4; i++) {
        int gr = row0 + tr + 16 * i;
        int u = u0 + 2 * c;
        float2 ai = unpk(acc2[i][0]);
        float2 ag = unpk(acc2[i][2]);
        float2 ao = unpk(acc2[i][3]);
        float2 b1i = *(const float2*)&b_ih[u],       b2i = *(const float2*)&b_hh[u];
        float2 b1g = *(const float2*)&b_ih[256 + u], b2g = *(const float2*)&b_hh[256 + u];
        float2 b1o = *(const float2*)&b_ih[384 + u], b2o = *(const float2*)&b_hh[384 + u];
        float2 hn;
        {
            float iv = sigf(ai.x + b1i.x + b2i.x);
            float gv = tanhf(ag.x + b1g.x + b2g.x);
            float ov = sigf(ao.x + b1o.x + b2o.x);
            float cn = iv * gv;
            hn.x = ov * tanhf(cn);
        }
        {
            float iv = sigf(ai.y + b1i.y + b2i.y);
            float gv = tanhf(ag.y + b1g.y + b2g.y);
            float ov = sigf(ao.y + b1o.y + b2o.y);
            float cn = iv * gv;
            hn.y = ov * tanhf(cn);
        }
        *(float2*)&g_hn[gr * HH + u] = hn;
    }
}

// =====================================================================
// Kernel 5: k/v projection GEMM, split K|V across CTAs.
//   64 rows/block over B*N rows, 128 cols (ch=0: Wk, ch=1: Wv), K=128.
// =====================================================================
__global__ __launch_bounds__(512, 2)
void k_kv(const float* __restrict__ ipw,
          const float* __restrict__ ipb) {
    extern __shared__ float sm[];
    float* sW  = sm;                  // 128*SWK
    float* sHn = sm + 128 * SWK;      // 64*129
    const int tid  = threadIdx.x;
    const int ch   = blockIdx.x & 1;          // 0 = K, 1 = V
    const int row0 = (blockIdx.x >> 1) * 64;

    for (int i = tid; i < 128 * 128; i += 512) {
        int e = i & 127, j = i >> 7;
        sW[e * SWK + j] = ipw[(HH + ch * HH + j) * HH + e];
    }
    for (int i = tid; i < 64 * HH; i += 512) {
        int r = i >> 7, col = i & 127;
        sHn[r * 129 + col] = g_hn[row0 * HH + i];
    }
    __syncthreads();

    const int c  = tid & 31;
    const int tr = tid >> 5;
    unsigned long long acc2[4][2];
    #pragma unroll
    for (int i = 0; i < 4; i++)
        #pragma unroll
        for (int m = 0; m < 2; m++) acc2[i][m] = 0ull;

    #pragma unroll 4
    for (int e = 0; e < HH; e++) {
        unsigned long long em2[4];
        #pragma unroll
        for (int i = 0; i < 4; i++) em2[i] = dup2(sHn[(tr + 16 * i) * 129 + e]);
        const float* wr = &sW[e * SWK + 2 * c];
        #pragma unroll
        for (int m = 0; m < 2; m++) {
            unsigned long long wp = *(const unsigned long long*)(wr + 64 * m);
            #pragma unroll
            for (int i = 0; i < 4; i++) ffma2(acc2[i][m], em2[i], wp);
        }
    }
    #pragma unroll
    for (int i = 0; i < 4; i++) {
        int gr = row0 + tr + 16 * i;
        #pragma unroll
        for (int m = 0; m < 2; m++) {
            int col = 64 * m + 2 * c;
            float2 v = unpk(acc2[i][m]);
            float2 bb = *(const float2*)&ipb[HH + ch * HH + col];
            v.x += bb.x; v.y += bb.y;
            *(float2*)&g_kv[gr * 256 + ch * HH + col] = v;
        }
    }
}

// =====================================================================
// Kernel 6: attention + heads. 512 thr = 4 lanes of 128, 4 batches/block.
// =====================================================================
#define LANE_SM 9160
__global__ __launch_bounds__(512, 1)
void k_attn2(const float* __restrict__ ipw,
             const float* __restrict__ ipb,
             const float* __restrict__ opw,
             const float* __restrict__ opb,
             const int*   __restrict__ cnts,
             const float* __restrict__ tW1,
             const float* __restrict__ tb1,
             const float* __restrict__ tW2,
             const float* __restrict__ tb2,
             const float* __restrict__ pW,
             const float* __restrict__ pb,
             float* __restrict__ out) {
    extern __shared__ float sm[];
    const int tid  = threadIdx.x;
    const int lane = tid >> 7;
    const int ltid = tid & 127;
    const int b    = blockIdx.x * 4 + lane;

    float* L    = sm + lane * LANE_SM;
    float* sK   = L;            // 32*129
    float* sV   = L + 4128;     // 32*129
    float* sHt  = L + 8256;     // 128
    float* sQ   = L + 8384;     // 128
    float* sWg  = L + 8512;     // 128
    float* sAt  = L + 8640;     // 128
    float* sHc  = L + 8768;     // 256
    float* sHid = L + 9024;     // 128
    float* sLg  = L + 9152;     // 4

    for (int i = ltid; i < NNB * HH; i += 128) {
        int n = i >> 7, col = i & 127;
        sK[n * 129 + col] = g_kv[(b * NNB + n) * 256 + col];
        sV[n * 129 + col] = g_kv[(b * NNB + n) * 256 + HH + col];
    }
    sHt[ltid] = g_h[b * HH + ltid];
    __syncthreads();

    // ---- q = h_t @ Wq^T + bq ----
    {
        float a = ipb[ltid];
        const float* w = &ipw[ltid * HH];
        #pragma unroll 8
        for (int h = 0; h < HH; h++) a = fmaf(sHt[h], w[h], a);
        sQ[ltid] = a;
    }
    __syncthreads();

    const int cnt = cnts[b];

    // ---- scores + masked softmax (warp per head) ----
    {
        int n = ltid & 31, hd = ltid >> 5;
        float s = 0.0f;
        #pragma unroll
        for (int d = 0; d < HD; d++)
            s = fmaf(sQ[hd * 32 + d], sK[n * 129 + hd * 32 + d], s);
        s *= 0.17677669529663689f;       // 1/sqrt(32)
        s = (n < cnt) ? s : -1e9f;
        float mx = s;
        #pragma unroll
        for (int o = 16; o > 0; o >>= 1)
            mx = fmaxf(mx, __shfl_xor_sync(0xffffffffu, mx, o));
        float ev = __expf(s - mx);
        float sum = ev;
        #pragma unroll
        for (int o = 16; o > 0; o >>= 1)
            sum += __shfl_xor_sync(0xffffffffu, sum, o);
        sWg[ltid] = ev / sum;
    }
    __syncthreads();

    // ---- attn = sum_n w[head,n] * v[n,:] ----
    {
        int hd = ltid >> 5;
        float a = 0.0f;
        #pragma unroll
        for (int n = 0; n < NNB; n++)
            a = fmaf(sWg[hd * 32 + n], sV[n * 129 + ltid], a);
        sAt[ltid] = a;
    }
    __syncthreads();

    // ---- out_proj + h_comb; attn_weights ----
    {
        float a = opb[ltid];
        const float* w = &opw[ltid * HH];
        #pragma unroll 8
        for (int h = 0; h < HH; h++) a = fmaf(sAt[h], w[h], a);
        sHc[ltid]       = sHt[ltid];
        sHc[128 + ltid] = (cnt > 0) ? a : 0.0f;
    }
    if (ltid < 32) {
        float aw = 0.25f * (sWg[ltid] + sWg[32 + ltid] + sWg[64 + ltid] + sWg[96 + ltid]);
        out[AW_OFF + b * NNB + ltid] = (ltid < cnt) ? aw : 0.0f;
    }
    __syncthreads();

    // ---- traj hidden ----
    {
        float a = tb1[ltid];
        const float* w = &tW1[ltid * 256];
        #pragma unroll 8
        for (int h = 0; h < 256; h++) a = fmaf(sHc[h], w[h], a);
        sHid[ltid] = fmaxf(a, 0.0f);
    }
    __syncthreads();

    // ---- traj output + prob logits (disjoint thread ranges) ----
    if (ltid < 36) {
        float a = tb2[ltid];
        const float* w = &tW2[ltid * HH];
        #pragma unroll 8
        for (int j = 0; j < HH; j++) a = fmaf(sHid[j], w[j], a);
        out[TRAJ_OFF + b * 36 + ltid] = a;
    }
    if (ltid >= 64 && ltid < 64 + KK) {
        int k = ltid - 64;
        float a = pb[k];
        const float* w = &pW[k * 256];
        #pragma unroll 8
        for (int h = 0; h < 256; h++) a = fmaf(sHc[h], w[h], a);
        sLg[k] = a;
    }
    __syncthreads();
    if (ltid < KK) {
        float m = fmaxf(sLg[0], fmaxf(sLg[1], sLg[2]));
        float e0 = __expf(sLg[0] - m);
        float e1 = __expf(sLg[1] - m);
        float e2 = __expf(sLg[2] - m);
        out[PROB_OFF + b * KK + ltid] = __expf(sLg[ltid] - m) / (e0 + e1 + e2);
    }
}

// =====================================================================
// Launch
// =====================================================================
extern "C" void kernel_launch(void* const* d_in, const int* in_sizes, int n_in,
                              void* d_out, int out_size) {
    (void)in_sizes; (void)n_in; (void)out_size;
    const float* x    = (const float*)d_in[0];
    const float* nb   = (const float*)d_in[1];
    const int*   cnts = (const int*)  d_in[2];
    const float* embW = (const float*)d_in[3];
    const float* embB = (const float*)d_in[4];
    const float* W_ih = (const float*)d_in[5];
    const float* W_hh = (const float*)d_in[6];
    const float* b_ih = (const float*)d_in[7];
    const float* b_hh = (const float*)d_in[8];
    const float* ipw  = (const float*)d_in[9];
    const float* ipb  = (const float*)d_in[10];
    const float* opw  = (const float*)d_in[11];
    const float* opb  = (const float*)d_in[12];
    const float* tW1  = (const float*)d_in[13];
    const float* tb1  = (const float*)d_in[14];
    const float* tW2  = (const float*)d_in[15];
    const float* tb2  = (const float*)d_in[16];
    const float* pW   = (const float*)d_in[17];
    const float* pb   = (const float*)d_in[18];
    float* out = (float*)d_out;

    const int SM_T = (64 * SWT + 64 * 64 + 64 * 8) * 4;     // ~84.5 KB
    const int SM_L = (64 * SWT + 64 * 128) * 4;             // ~98.8 KB
    const int SM_K = (128 * SWK + 64 * 129) * 4;            // ~99.6 KB
    const int SM_A = (4 * LANE_SM) * 4;                     // ~146.6 KB

    cudaFuncSetAttribute(k_target_in, cudaFuncAttributeMaxDynamicSharedMemorySize, SM_T);
    cudaFuncSetAttribute(k_lstm_step, cudaFuncAttributeMaxDynamicSharedMemorySize, SM_L);
    cudaFuncSetAttribute(k_neighbor,  cudaFuncAttributeMaxDynamicSharedMemorySize, SM_T);
    cudaFuncSetAttribute(k_kv,        cudaFuncAttributeMaxDynamicSharedMemorySize, SM_K);
    cudaFuncSetAttribute(k_attn2,     cudaFuncAttributeMaxDynamicSharedMemorySize, SM_A);

    // target chain
    k_target_in<<<(BB * TT / 64) * 2, 512, SM_T>>>(x, embW, embB, W_ih);
    k_lstm0<<<(BB * HH + 255) / 256, 256>>>(b_ih, b_hh);
    for (int t = 1; t < TT; t++)
        k_lstm_step<<<(BB / 64) * 2, 512, SM_L>>>(W_hh, b_ih, b_hh, t);

    // neighbor chain
    k_neighbor<<<(BB * NNB / 64) * 2, 512, SM_T>>>(nb, embW, embB, W_ih, b_ih, b_hh);
    k_kv<<<(BB * NNB / 64) * 2, 512, SM_K>>>(ipw, ipb);

    // attention + heads
    k_attn2<<<BB / 4, 512, SM_A>>>(ipw, ipb, opw, opb, cnts,
                                   tW1, tb1, tW2, tb2, pW, pb, out);
}

// round 9
// speedup vs baseline: 3.4615x; 2.4296x over previous
#include <cuda_runtime.h>
#include <cuda_bf16.h>
#include <math.h>

// ---------------- problem constants ----------------
#define BB   16384
#define TT   4
#define FF   7
#define EE   64
#define HH   128
#define G4   512        // 4*H
#define NNB  32         // neighbors
#define NH   4
#define HD   32
#define KK   3

// output layout: traj (B*36), probs (B*3), attn_weights (B*32)
#define TRAJ_OFF 0
#define PROB_OFF (BB * 36)
#define AW_OFF   (BB * 36 + BB * 3)

#define SWT 258         // 256-col weight tile stride (even -> aligned pairs)
#define SWK 130         // 128-col weight tile stride

// ---------------- scratch (__device__ globals) ----------------
static __device__ float g_preact_x[BB * TT * G4];       // 134 MB
static __device__ float g_h[BB * HH];
static __device__ float g_c[BB * HH];
static __device__ float g_hn[BB * NNB * HH];            // 268 MB
static __device__ float g_kv[BB * NNB * 2 * HH];        // 536 MB (K | V per row)
static __device__ float g_q[BB * HH];
static __device__ float g_att[BB * HH];

__device__ __forceinline__ float sigf(float x) {
    return 1.0f / (1.0f + __expf(-x));
}

// ---- packed f32x2 helpers ----
__device__ __forceinline__ void ffma2(unsigned long long& d,
                                      unsigned long long a,
                                      unsigned long long b) {
    asm("fma.rn.f32x2 %0, %1, %2, %0;" : "+l"(d) : "l"(a), "l"(b));
}
__device__ __forceinline__ unsigned long long dup2(float x) {
    unsigned long long r;
    unsigned u = __float_as_uint(x);
    asm("mov.b64 %0, {%1, %1};" : "=l"(r) : "r"(u));
    return r;
}
__device__ __forceinline__ float2 unpk(unsigned long long v) {
    unsigned lo, hi;
    asm("mov.b64 {%0, %1}, %2;" : "=r"(lo), "=r"(hi) : "l"(v));
    return make_float2(__uint_as_float(lo), __uint_as_float(hi));
}

// =====================================================================
// Kernel 1: target embed + input GEMM, unit-split.
// =====================================================================
__global__ __launch_bounds__(512, 2)
void k_target_in(const float* __restrict__ x,
                 const float* __restrict__ embW,
                 const float* __restrict__ embB,
                 const float* __restrict__ W_ih) {
    extern __shared__ float sm[];
    float* sW = sm;                      // 64*SWT
    float* sE = sm + 64 * SWT;           // 64*64
    float* sX = sE + 64 * 64;            // 64*8
    const int tid  = threadIdx.x;
    const int ch   = blockIdx.x & 1;
    const int row0 = (blockIdx.x >> 1) * 64;
    const int u0   = ch * 64;

    for (int i = tid; i < 256 * 64; i += 512) {
        int e = i & 63, col = i >> 6;
        int gt = col >> 6, j = col & 63;
        sW[e * SWT + col] = W_ih[(128 * gt + u0 + j) * EE + e];
    }
    for (int i = tid; i < 64 * FF; i += 512) {
        int r = i / FF, f = i % FF;
        sX[r * 8 + f] = x[(row0 + r) * FF + f];
    }
    __syncthreads();
    for (int i = tid; i < 64 * EE; i += 512) {
        int r = i >> 6, e = i & 63;
        float a = embB[e];
        #pragma unroll
        for (int f = 0; f < FF; f++) a += sX[r * 8 + f] * embW[e * FF + f];
        sE[i] = fmaxf(a, 0.0f);
    }
    __syncthreads();

    const int c  = tid & 31;
    const int tr = tid >> 5;
    unsigned long long acc2[4][4];
    #pragma unroll
    for (int i = 0; i < 4; i++)
        #pragma unroll
        for (int m = 0; m < 4; m++) acc2[i][m] = 0ull;

    #pragma unroll 4
    for (int e = 0; e < EE; e++) {
        unsigned long long em2[4];
        #pragma unroll
        for (int i = 0; i < 4; i++) em2[i] = dup2(sE[(tr + 16 * i) * 64 + e]);
        const float* wr = &sW[e * SWT + 2 * c];
        #pragma unroll
        for (int m = 0; m < 4; m++) {
            unsigned long long wp = *(const unsigned long long*)(wr + 64 * m);
            #pragma unroll
            for (int i = 0; i < 4; i++) ffma2(acc2[i][m], em2[i], wp);
        }
    }
    #pragma unroll
    for (int i = 0; i < 4; i++) {
        int row = row0 + tr + 16 * i;
        #pragma unroll
        for (int gt = 0; gt < 4; gt++) {
            float2 v = unpk(acc2[i][gt]);
            *(float2*)&g_preact_x[row * G4 + 128 * gt + u0 + 2 * c] = v;
        }
    }
}

// =====================================================================
// Kernel 2: LSTM step 0 (h=c=0)
// =====================================================================
__global__ void k_lstm0(const float* __restrict__ b_ih,
                        const float* __restrict__ b_hh) {
    int idx = blockIdx.x * blockDim.x + threadIdx.x;
    if (idx >= BB * HH) return;
    int b = idx >> 7, u = idx & 127;
    const float* px = &g_preact_x[(b * TT) * G4];
    float iv = sigf(px[u] + b_ih[u] + b_hh[u]);
    float gv = tanhf(px[256 + u] + b_ih[256 + u] + b_hh[256 + u]);
    float ov = sigf(px[384 + u] + b_ih[384 + u] + b_hh[384 + u]);
    float cn = iv * gv;
    g_c[idx] = cn;
    g_h[idx] = ov * tanhf(cn);
}

// =====================================================================
// Kernel 3: LSTM step t
// =====================================================================
__global__ __launch_bounds__(512, 2)
void k_lstm_step(const float* __restrict__ W_hh,
                 const float* __restrict__ b_ih,
                 const float* __restrict__ b_hh,
                 int t) {
    extern __shared__ float sm[];
    float* sW = sm;                 // 64*SWT
    float* sH = sm + 64 * SWT;      // 64*128
    const int tid = threadIdx.x;
    const int ch  = blockIdx.x & 1;
    const int b0  = (blockIdx.x >> 1) * 64;
    const int u0  = ch * 64;

    for (int i = tid; i < 64 * HH; i += 512) sH[i] = g_h[b0 * HH + i];

    const int c  = tid & 31;
    const int tr = tid >> 5;
    unsigned long long acc2[4][4];
    #pragma unroll
    for (int i = 0; i < 4; i++)
        #pragma unroll
        for (int m = 0; m < 4; m++) acc2[i][m] = 0ull;

    for (int half = 0; half < 2; half++) {
        __syncthreads();
        for (int i = tid; i < 256 * 64; i += 512) {
            int e = i & 63, col = i >> 6;
            int gt = col >> 6, j = col & 63;
            sW[e * SWT + col] = W_hh[(128 * gt + u0 + j) * HH + half * 64 + e];
        }
        __syncthreads();
        #pragma unroll 4
        for (int e = 0; e < 64; e++) {
            unsigned long long em2[4];
            #pragma unroll
            for (int i = 0; i < 4; i++)
                em2[i] = dup2(sH[(tr + 16 * i) * HH + half * 64 + e]);
            const float* wr = &sW[e * SWT + 2 * c];
            #pragma unroll
            for (int m = 0; m < 4; m++) {
                unsigned long long wp = *(const unsigned long long*)(wr + 64 * m);
                #pragma unroll
                for (int i = 0; i < 4; i++) ffma2(acc2[i][m], em2[i], wp);
            }
        }
    }

    #pragma unroll
    for (int i = 0; i < 4; i++) {
        int b = b0 + tr + 16 * i;
        const float* px = &g_preact_x[(b * TT + t) * G4];
        int u = u0 + 2 * c;
        float2 ai = unpk(acc2[i][0]);
        float2 af = unpk(acc2[i][1]);
        float2 ag = unpk(acc2[i][2]);
        float2 ao = unpk(acc2[i][3]);
        float2 pxi = *(const float2*)&px[u];
        float2 pxf = *(const float2*)&px[128 + u];
        float2 pxg = *(const float2*)&px[256 + u];
        float2 pxo = *(const float2*)&px[384 + u];
        float2 b1i = *(const float2*)&b_ih[u],       b2i = *(const float2*)&b_hh[u];
        float2 b1f = *(const float2*)&b_ih[128 + u], b2f = *(const float2*)&b_hh[128 + u];
        float2 b1g = *(const float2*)&b_ih[256 + u], b2g = *(const float2*)&b_hh[256 + u];
        float2 b1o = *(const float2*)&b_ih[384 + u], b2o = *(const float2*)&b_hh[384 + u];
        float2 cp = *(const float2*)&g_c[b * HH + u];
        float2 cn, hn;
        {
            float iv = sigf(ai.x + pxi.x + b1i.x + b2i.x);
            float fv = sigf(af.x + pxf.x + b1f.x + b2f.x);
            float gv = tanhf(ag.x + pxg.x + b1g.x + b2g.x);
            float ov = sigf(ao.x + pxo.x + b1o.x + b2o.x);
            cn.x = fv * cp.x + iv * gv;
            hn.x = ov * tanhf(cn.x);
        }
        {
            float iv = sigf(ai.y + pxi.y + b1i.y + b2i.y);
            float fv = sigf(af.y + pxf.y + b1f.y + b2f.y);
            float gv = tanhf(ag.y + pxg.y + b1g.y + b2g.y);
            float ov = sigf(ao.y + pxo.y + b1o.y + b2o.y);
            cn.y = fv * cp.y + iv * gv;
            hn.y = ov * tanhf(cn.y);
        }
        *(float2*)&g_c[b * HH + u] = cn;
        *(float2*)&g_h[b * HH + u] = hn;
    }
}

// =====================================================================
// Kernel 4: neighbor encoder
// =====================================================================
__global__ __launch_bounds__(512, 2)
void k_neighbor(const float* __restrict__ nb,
                const float* __restrict__ embW,
                const float* __restrict__ embB,
                const float* __restrict__ W_ih,
                const float* __restrict__ b_ih,
                const float* __restrict__ b_hh) {
    extern __shared__ float sm[];
    float* sW = sm;                      // 64*SWT
    float* sE = sm + 64 * SWT;           // 64*64
    float* sX = sE + 64 * 64;            // 64*8
    const int tid  = threadIdx.x;
    const int ch   = blockIdx.x & 1;
    const int row0 = (blockIdx.x >> 1) * 64;
    const int u0   = ch * 64;

    for (int i = tid; i < 256 * 64; i += 512) {
        int e = i & 63, col = i >> 6;
        int gt = col >> 6, j = col & 63;
        sW[e * SWT + col] = W_ih[(128 * gt + u0 + j) * EE + e];
    }
    for (int i = tid; i < 64 * FF; i += 512) {
        int r = i / FF, f = i % FF;
        sX[r * 8 + f] = nb[(row0 + r) * FF + f];
    }
    __syncthreads();
    for (int i = tid; i < 64 * EE; i += 512) {
        int r = i >> 6, e = i & 63;
        float a = embB[e];
        #pragma unroll
        for (int f = 0; f < FF; f++) a += sX[r * 8 + f] * embW[e * FF + f];
        sE[i] = fmaxf(a, 0.0f);
    }
    __syncthreads();

    const int c  = tid & 31;
    const int tr = tid >> 5;
    unsigned long long acc2[4][4];
    #pragma unroll
    for (int i = 0; i < 4; i++)
        #pragma unroll
        for (int m = 0; m < 4; m++) acc2[i][m] = 0ull;

    #pragma unroll 4
    for (int e = 0; e < EE; e++) {
        unsigned long long em2[4];
        #pragma unroll
        for (int i = 0; i < 4; i++) em2[i] = dup2(sE[(tr + 16 * i) * 64 + e]);
        const float* wr = &sW[e * SWT + 2 * c];
        #pragma unroll
        for (int m = 0; m < 4; m++) {
            unsigned long long wp = *(const unsigned long long*)(wr + 64 * m);
            #pragma unroll
            for (int i = 0; i < 4; i++) ffma2(acc2[i][m], em2[i], wp);
        }
    }
    #pragma unroll
    for (int i = 0; i < 4; i++) {
        int gr = row0 + tr + 16 * i;
        int u = u0 + 2 * c;
        float2 ai = unpk(acc2[i][0]);
        float2 ag = unpk(acc2[i][2]);
        float2 ao = unpk(acc2[i][3]);
        float2 b1i = *(const float2*)&b_ih[u],       b2i = *(const float2*)&b_hh[u];
        float2 b1g = *(const float2*)&b_ih[256 + u], b2g = *(const float2*)&b_hh[256 + u];
        float2 b1o = *(const float2*)&b_ih[384 + u], b2o = *(const float2*)&b_hh[384 + u];
        float2 hn;
        {
            float iv = sigf(ai.x + b1i.x + b2i.x);
            float gv = tanhf(ag.x + b1g.x + b2g.x);
            float ov = sigf(ao.x + b1o.x + b2o.x);
            float cn = iv * gv;
            hn.x = ov * tanhf(cn);
        }
        {
            float iv = sigf(ai.y + b1i.y + b2i.y);
            float gv = tanhf(ag.y + b1g.y + b2g.y);
            float ov = sigf(ao.y + b1o.y + b2o.y);
            float cn = iv * gv;
            hn.y = ov * tanhf(cn);
        }
        *(float2*)&g_hn[gr * HH + u] = hn;
    }
}

// =====================================================================
// Kernel 5: k/v projection GEMM
// =====================================================================
__global__ __launch_bounds__(512, 2)
void k_kv(const float* __restrict__ ipw,
          const float* __restrict__ ipb) {
    extern __shared__ float sm[];
    float* sW  = sm;                  // 128*SWK
    float* sHn = sm + 128 * SWK;      // 64*129
    const int tid  = threadIdx.x;
    const int ch   = blockIdx.x & 1;          // 0 = K, 1 = V
    const int row0 = (blockIdx.x >> 1) * 64;

    for (int i = tid; i < 128 * 128; i += 512) {
        int e = i & 127, j = i >> 7;
        sW[e * SWK + j] = ipw[(HH + ch * HH + j) * HH + e];
    }
    for (int i = tid; i < 64 * HH; i += 512) {
        int r = i >> 7, col = i & 127;
        sHn[r * 129 + col] = g_hn[row0 * HH + i];
    }
    __syncthreads();

    const int c  = tid & 31;
    const int tr = tid >> 5;
    unsigned long long acc2[4][2];
    #pragma unroll
    for (int i = 0; i < 4; i++)
        #pragma unroll
        for (int m = 0; m < 2; m++) acc2[i][m] = 0ull;

    #pragma unroll 4
    for (int e = 0; e < HH; e++) {
        unsigned long long em2[4];
        #pragma unroll
        for (int i = 0; i < 4; i++) em2[i] = dup2(sHn[(tr + 16 * i) * 129 + e]);
        const float* wr = &sW[e * SWK + 2 * c];
        #pragma unroll
        for (int m = 0; m < 2; m++) {
            unsigned long long wp = *(const unsigned long long*)(wr + 64 * m);
            #pragma unroll
            for (int i = 0; i < 4; i++) ffma2(acc2[i][m], em2[i], wp);
        }
    }
    #pragma unroll
    for (int i = 0; i < 4; i++) {
        int gr = row0 + tr + 16 * i;
        #pragma unroll
        for (int m = 0; m < 2; m++) {
            int col = 64 * m + 2 * c;
            float2 v = unpk(acc2[i][m]);
            float2 bb = *(const float2*)&ipb[HH + ch * HH + col];
            v.x += bb.x; v.y += bb.y;
            *(float2*)&g_kv[gr * 256 + ch * HH + col] = v;
        }
    }
}

// =====================================================================
// Kernel 6: q projection GEMM over B rows: g_q = g_h @ Wq^T + bq.
// =====================================================================
__global__ __launch_bounds__(512, 2)
void k_q(const float* __restrict__ ipw,
         const float* __restrict__ ipb) {
    extern __shared__ float sm[];
    float* sW = sm;                  // 128*SWK
    float* sH = sm + 128 * SWK;      // 64*129
    const int tid  = threadIdx.x;
    const int row0 = blockIdx.x * 64;

    for (int i = tid; i < 128 * 128; i += 512) {
        int e = i & 127, j = i >> 7;
        sW[e * SWK + j] = ipw[j * HH + e];      // Wq rows 0..127
    }
    for (int i = tid; i < 64 * HH; i += 512) {
        int r = i >> 7, col = i & 127;
        sH[r * 129 + col] = g_h[row0 * HH + i];
    }
    __syncthreads();

    const int c  = tid & 31;
    const int tr = tid >> 5;
    unsigned long long acc2[4][2];
    #pragma unroll
    for (int i = 0; i < 4; i++)
        #pragma unroll
        for (int m = 0; m < 2; m++) acc2[i][m] = 0ull;

    #pragma unroll 4
    for (int e = 0; e < HH; e++) {
        unsigned long long em2[4];
        #pragma unroll
        for (int i = 0; i < 4; i++) em2[i] = dup2(sH[(tr + 16 * i) * 129 + e]);
        const float* wr = &sW[e * SWK + 2 * c];
        #pragma unroll
        for (int m = 0; m < 2; m++) {
            unsigned long long wp = *(const unsigned long long*)(wr + 64 * m);
            #pragma unroll
            for (int i = 0; i < 4; i++) ffma2(acc2[i][m], em2[i], wp);
        }
    }
    #pragma unroll
    for (int i = 0; i < 4; i++) {
        int gr = row0 + tr + 16 * i;
        #pragma unroll
        for (int m = 0; m < 2; m++) {
            int col = 64 * m + 2 * c;
            float2 v = unpk(acc2[i][m]);
            float2 bb = *(const float2*)&ipb[col];
            v.x += bb.x; v.y += bb.y;
            *(float2*)&g_q[gr * HH + col] = v;
        }
    }
}

// =====================================================================
// Kernel 7: attention core. 512 thr = 4 lanes of 128, 4 batches/block.
// =====================================================================
#define ALANE 4384      // 32*129 (sK) + 128 (sQ) + 128 (sWg)
__global__ __launch_bounds__(512, 2)
void k_attn3(const int* __restrict__ cnts,
             float* __restrict__ out) {
    extern __shared__ float sm[];
    const int tid  = threadIdx.x;
    const int lane = tid >> 7;
    const int ltid = tid & 127;
    const int b    = blockIdx.x * 4 + lane;

    float* L   = sm + lane * ALANE;
    float* sK  = L;            // 32*129
    float* sQ  = L + 4128;     // 128
    float* sWg = L + 4256;     // 128

    for (int i = ltid; i < NNB * HH; i += 128) {
        int n = i >> 7, col = i & 127;
        sK[n * 129 + col] = g_kv[(b * NNB + n) * 256 + col];
    }
    sQ[ltid] = g_q[b * HH + ltid];
    __syncthreads();

    const int cnt = cnts[b];

    // ---- scores + masked softmax (warp per head) ----
    {
        int n = ltid & 31, hd = ltid >> 5;
        float s = 0.0f;
        #pragma unroll
        for (int d = 0; d < HD; d++)
            s = fmaf(sQ[hd * 32 + d], sK[n * 129 + hd * 32 + d], s);
        s *= 0.17677669529663689f;       // 1/sqrt(32)
        s = (n < cnt) ? s : -1e9f;
        float mx = s;
        #pragma unroll
        for (int o = 16; o > 0; o >>= 1)
            mx = fmaxf(mx, __shfl_xor_sync(0xffffffffu, mx, o));
        float ev = __expf(s - mx);
        float sum = ev;
        #pragma unroll
        for (int o = 16; o > 0; o >>= 1)
            sum += __shfl_xor_sync(0xffffffffu, sum, o);
        sWg[ltid] = ev / sum;
    }
    __syncthreads();

    // ---- attn = sum_n w[head,n] * v[n,:]; V read coalesced from global ----
    {
        int hd = ltid >> 5;
        float a = 0.0f;
        const float* vbase = &g_kv[b * NNB * 256 + HH + ltid];
        #pragma unroll 8
        for (int n = 0; n < NNB; n++)
            a = fmaf(sWg[hd * 32 + n], vbase[n * 256], a);
        g_att[b * HH + ltid] = a;
    }
    if (ltid < 32) {
        float aw = 0.25f * (sWg[ltid] + sWg[32 + ltid] + sWg[64 + ltid] + sWg[96 + ltid]);
        out[AW_OFF + b * NNB + ltid] = (ltid < cnt) ? aw : 0.0f;
    }
}

// =====================================================================
// Kernel 8: output heads, batched GEMM stages. 512 thr, 64 rows/block.
// =====================================================================
__global__ __launch_bounds__(512, 1)
void k_out(const float* __restrict__ opw,
           const float* __restrict__ opb,
           const int*   __restrict__ cnts,
           const float* __restrict__ tW1,
           const float* __restrict__ tb1,
           const float* __restrict__ tW2,
           const float* __restrict__ tb2,
           const float* __restrict__ pW,
           const float* __restrict__ pb,
           float* __restrict__ out) {
    extern __shared__ float sm[];
    float* sW   = sm;                       // 128*SWK = 16640
    float* sHc  = sW  + 128 * SWK;          // 64*258 = 16512
    float* sHid = sHc + 64 * 258;           // 64*130 = 8320
    float* sIn  = sHid + 64 * 130;          // 64*129 = 8256 (g_att; reused for prob logits)
    int*   sCnt = (int*)(sIn + 64 * 129);   // 64

    const int tid = threadIdx.x;
    const int b0  = blockIdx.x * 64;

    for (int i = tid; i < 128 * 128; i += 512) {
        int e = i & 127, j = i >> 7;
        sW[e * SWK + j] = opw[j * HH + e];
    }
    for (int i = tid; i < 64 * HH; i += 512) {
        int r = i >> 7, col = i & 127;
        sIn[r * 129 + col] = g_att[b0 * HH + i];
        sHc[r * 258 + col] = g_h[b0 * HH + i];
    }
    if (tid < 64) sCnt[tid] = cnts[b0 + tid];
    __syncthreads();

    const int c  = tid & 31;
    const int tr = tid >> 5;

    // ---- Stage A: out_proj (64 x 128, K=128) ----
    {
        unsigned long long acc2[4][2];
        #pragma unroll
        for (int i = 0; i < 4; i++)
            #pragma unroll
            for (int m = 0; m < 2; m++) acc2[i][m] = 0ull;
        #pragma unroll 4
        for (int e = 0; e < HH; e++) {
            unsigned long long em2[4];
            #pragma unroll
            for (int i = 0; i < 4; i++) em2[i] = dup2(sIn[(tr + 16 * i) * 129 + e]);
            const float* wr = &sW[e * SWK + 2 * c];
            #pragma unroll
            for (int m = 0; m < 2; m++) {
                unsigned long long wp = *(const unsigned long long*)(wr + 64 * m);
                #pragma unroll
                for (int i = 0; i < 4; i++) ffma2(acc2[i][m], em2[i], wp);
            }
        }
        #pragma unroll
        for (int i = 0; i < 4; i++) {
            int r = tr + 16 * i;
            int msk = (sCnt[r] > 0);
            #pragma unroll
            for (int m = 0; m < 2; m++) {
                int col = 64 * m + 2 * c;
                float2 v = unpk(acc2[i][m]);
                float2 bb = *(const float2*)&opb[col];
                sHc[r * 258 + 128 + col]     = msk ? (v.x + bb.x) : 0.0f;
                sHc[r * 258 + 128 + col + 1] = msk ? (v.y + bb.y) : 0.0f;
            }
        }
    }

    // ---- Stage B: hid = relu(sHc @ tW1^T + tb1), K=256 in two halves ----
    {
        unsigned long long acc2[4][2];
        #pragma unroll
        for (int i = 0; i < 4; i++)
            #pragma unroll
            for (int m = 0; m < 2; m++) acc2[i][m] = 0ull;
        for (int half = 0; half < 2; half++) {
            __syncthreads();
            for (int i = tid; i < 128 * 128; i += 512) {
                int e = i & 127, j = i >> 7;
                sW[e * SWK + j] = tW1[j * 256 + half * 128 + e];
            }
            __syncthreads();
            #pragma unroll 4
            for (int e = 0; e < HH; e++) {
                unsigned long long em2[4];
                #pragma unroll
                for (int i = 0; i < 4; i++)
                    em2[i] = dup2(sHc[(tr + 16 * i) * 258 + half * 128 + e]);
                const float* wr = &sW[e * SWK + 2 * c];
                #pragma unroll
                for (int m = 0; m < 2; m++) {
                    unsigned long long wp = *(const unsigned long long*)(wr + 64 * m);
                    #pragma unroll
                    for (int i = 0; i < 4; i++) ffma2(acc2[i][m], em2[i], wp);
                }
            }
        }
        #pragma unroll
        for (int i = 0; i < 4; i++) {
            int r = tr + 16 * i;
            #pragma unroll
            for (int m = 0; m < 2; m++) {
                int col = 64 * m + 2 * c;
                float2 v = unpk(acc2[i][m]);
                float2 bb = *(const float2*)&tb1[col];
                sHid[r * 130 + col]     = fmaxf(v.x + bb.x, 0.0f);
                sHid[r * 130 + col + 1] = fmaxf(v.y + bb.y, 0.0f);
            }
        }
    }
    __syncthreads();

    // ---- Stage C: stage tW2 (stride 132) and pW (stride 260) into sW ----
    for (int i = tid; i < 36 * 128; i += 512) {
        int col = i >> 7, h = i & 127;
        sW[col * 132 + h] = tW2[i];
    }
    for (int i = tid; i < KK * 256; i += 512) {
        int k = i >> 8, h = i & 255;
        sW[8192 + k * 260 + h] = pW[i];
    }
    __syncthreads();

    for (int idx = tid; idx < 64 * 36; idx += 512) {
        int r = idx / 36, col = idx % 36;
        float a = tb2[col];
        const float* w = &sW[col * 132];
        const float* hrow = &sHid[r * 130];
        #pragma unroll 8
        for (int h = 0; h < 128; h++) a = fmaf(hrow[h], w[h], a);
        out[TRAJ_OFF + (b0 + r) * 36 + col] = a;
    }
    if (tid < 192) {
        int r = tid / 3, k = tid % 3;
        float a = pb[k];
        const float* w = &sW[8192 + k * 260];
        const float* hrow = &sHc[r * 258];
        #pragma unroll 8
        for (int h = 0; h < 256; h++) a = fmaf(hrow[h], w[h], a);
        sIn[r * 3 + k] = a;
    }
    __syncthreads();
    if (tid < 64) {
        float l0 = sIn[tid * 3], l1 = sIn[tid * 3 + 1], l2 = sIn[tid * 3 + 2];
        float m = fmaxf(l0, fmaxf(l1, l2));
        float e0 = __expf(l0 - m), e1 = __expf(l1 - m), e2 = __expf(l2 - m);
        float inv = 1.0f / (e0 + e1 + e2);
        out[PROB_OFF + (b0 + tid) * 3 + 0] = e0 * inv;
        out[PROB_OFF + (b0 + tid) * 3 + 1] = e1 * inv;
        out[PROB_OFF + (b0 + tid) * 3 + 2] = e2 * inv;
    }
}

// =====================================================================
// Launch
// =====================================================================
extern "C" void kernel_launch(void* const* d_in, const int* in_sizes, int n_in,
                              void* d_out, int out_size) {
    (void)in_sizes; (void)n_in; (void)out_size;
    const float* x    = (const float*)d_in[0];
    const float* nb   = (const float*)d_in[1];
    const int*   cnts = (const int*)  d_in[2];
    const float* embW = (const float*)d_in[3];
    const float* embB = (const float*)d_in[4];
    const float* W_ih = (const float*)d_in[5];
    const float* W_hh = (const float*)d_in[6];
    const float* b_ih = (const float*)d_in[7];
    const float* b_hh = (const float*)d_in[8];
    const float* ipw  = (const float*)d_in[9];
    const float* ipb  = (const float*)d_in[10];
    const float* opw  = (const float*)d_in[11];
    const float* opb  = (const float*)d_in[12];
    const float* tW1  = (const float*)d_in[13];
    const float* tb1  = (const float*)d_in[14];
    const float* tW2  = (const float*)d_in[15];
    const float* tb2  = (const float*)d_in[16];
    const float* pW   = (const float*)d_in[17];
    const float* pb   = (const float*)d_in[18];
    float* out = (float*)d_out;

    const int SM_T  = (64 * SWT + 64 * 64 + 64 * 8) * 4;     // ~84.5 KB
    const int SM_L  = (64 * SWT + 64 * 128) * 4;             // ~98.8 KB
    const int SM_K  = (128 * SWK + 64 * 129) * 4;            // ~99.6 KB
    const int SM_A3 = (4 * ALANE) * 4;                       // ~70.1 KB
    const int SM_O  = (128 * SWK + 64 * 258 + 64 * 130 + 64 * 129 + 64) * 4;  // ~194.5 KB

    cudaFuncSetAttribute(k_target_in, cudaFuncAttributeMaxDynamicSharedMemorySize, SM_T);
    cudaFuncSetAttribute(k_lstm_step, cudaFuncAttributeMaxDynamicSharedMemorySize, SM_L);
    cudaFuncSetAttribute(k_neighbor,  cudaFuncAttributeMaxDynamicSharedMemorySize, SM_T);
    cudaFuncSetAttribute(k_kv,        cudaFuncAttributeMaxDynamicSharedMemorySize, SM_K);
    cudaFuncSetAttribute(k_q,         cudaFuncAttributeMaxDynamicSharedMemorySize, SM_K);
    cudaFuncSetAttribute(k_attn3,     cudaFuncAttributeMaxDynamicSharedMemorySize, SM_A3);
    cudaFuncSetAttribute(k_out,       cudaFuncAttributeMaxDynamicSharedMemorySize, SM_O);

    // target chain
    k_target_in<<<(BB * TT / 64) * 2, 512, SM_T>>>(x, embW, embB, W_ih);
    k_lstm0<<<(BB * HH + 255) / 256, 256>>>(b_ih, b_hh);
    for (int t = 1; t < TT; t++)
        k_lstm_step<<<(BB / 64) * 2, 512, SM_L>>>(W_hh, b_ih, b_hh, t);

    // neighbor chain
    k_neighbor<<<(BB * NNB / 64) * 2, 512, SM_T>>>(nb, embW, embB, W_ih, b_ih, b_hh);
    k_kv<<<(BB * NNB / 64) * 2, 512, SM_K>>>(ipw, ipb);

    // attention chain
    k_q<<<BB / 64, 512, SM_K>>>(ipw, ipb);
    k_attn3<<<BB / 4, 512, SM_A3>>>(cnts, out);
    k_out<<<BB / 64, 512, SM_O>>>(opw, opb, cnts, tW1, tb1, tW2, tb2, pW, pb, out);
}